// round 2
// baseline (speedup 1.0000x reference)
#include <cuda_runtime.h>
#include <cuda_bf16.h>
#include <math.h>

// ---------------- Problem constants (fixed shapes) ----------------
#define NNODES 50000
#define NEDGES 800000
#define INDIM  256
#define HDIM   96
#define OUTDIM 40
#define H4     24            // HDIM/4
#define BN_EPSF 1e-5f

// ---------------- Scratch (device globals; no allocation) ----------------
// 16-byte alignment is REQUIRED on everything accessed as float4 / red.v4.
__device__ float g_deg [NNODES];
__device__ float g_dinv[NNODES];
__device__ float g_norm[NEDGES];
__device__ int   g_row [NEDGES];
__device__ int   g_col [NEDGES];
__device__ __align__(16) float g_x0  [NNODES * HDIM];
__device__ __align__(16) float g_xcur[NNODES * HDIM];
__device__ __align__(16) float g_agg [NNODES * HDIM];   // agg, then h2 in-place
__device__ float g_sums[2 * HDIM];        // [0:96) sum, [96:192) sumsq
__device__ int   g_is64;

// ---------------- Index dtype detection + conversion ----------------
// If edge_index is int64, every odd 32-bit word (high half) of the first 1024
// elements is 0 (values in [0, 50000)). If int32, those words are random node
// ids — essentially never all zero.
__global__ void detect_idx(const void* p) {
    const int* q = (const int*)p;
    __shared__ int s;
    if (threadIdx.x == 0) s = 0;
    __syncthreads();
    int nz = 0;
    for (int i = threadIdx.x; i < 1024; i += 256) nz |= q[2 * i + 1];
    if (nz) atomicOr(&s, 1);
    __syncthreads();
    if (threadIdx.x == 0) g_is64 = (s == 0) ? 1 : 0;
}

__global__ void deg_init() {
    int i = blockIdx.x * 256 + threadIdx.x;
    if (i < NNODES) g_deg[i] = 1.0f;   // self-loop
}

// convert to int32 and count degrees (by col) in one pass
__global__ void convert_idx(const void* p) {
    int e = blockIdx.x * 256 + threadIdx.x;
    if (e >= NEDGES) return;
    int r, c;
    if (g_is64) {
        const long long* q = (const long long*)p;
        r = (int)q[e];
        c = (int)q[(long long)NEDGES + e];
    } else {
        const int* q = (const int*)p;
        r = q[e];
        c = q[NEDGES + e];
    }
    g_row[e] = r;
    g_col[e] = c;
    atomicAdd(&g_deg[c], 1.0f);
}

__global__ void dinv_kernel() {
    int i = blockIdx.x * 256 + threadIdx.x;
    if (i >= NNODES) return;
    float d = g_deg[i];
    g_dinv[i] = (d > 0.f) ? rsqrtf(d) : 0.f;
}

__global__ void norm_kernel() {
    int e = blockIdx.x * 256 + threadIdx.x;
    if (e >= NEDGES) return;
    g_norm[e] = g_dinv[g_row[e]] * g_dinv[g_col[e]];
}

// ---------------- fc1: relu(X @ W + b) -> g_x0, g_xcur ----------------
// Tile: 64 rows x 96 cols, K chunked by 32. 256 threads: (tx 0..31, ty 0..7),
// thread computes rows ty*8..+7, cols {tx, tx+32, tx+64}.
__global__ __launch_bounds__(256) void fc1_gemm(
    const float* __restrict__ X, const float* __restrict__ W,
    const float* __restrict__ b)
{
    __shared__ float As[64][32];
    __shared__ float Ws[32][96];
    int tid = threadIdx.x;
    int tx = tid & 31, ty = tid >> 5;
    int rowbase = blockIdx.x * 64;
    float acc[8][3] = {};
    for (int kc = 0; kc < INDIM; kc += 32) {
        #pragma unroll
        for (int i = 0; i < 8; i++) {
            int idx = tid + i * 256;
            int r = idx >> 5, k = idx & 31;
            int gr = rowbase + r;
            As[r][k] = (gr < NNODES) ? X[gr * INDIM + kc + k] : 0.f;
        }
        #pragma unroll
        for (int i = 0; i < 12; i++) {
            int idx = tid + i * 256;
            ((float*)Ws)[idx] = W[kc * HDIM + idx];
        }
        __syncthreads();
        #pragma unroll
        for (int kk = 0; kk < 32; kk++) {
            float w0 = Ws[kk][tx], w1 = Ws[kk][tx + 32], w2 = Ws[kk][tx + 64];
            #pragma unroll
            for (int i = 0; i < 8; i++) {
                float a = As[ty * 8 + i][kk];
                acc[i][0] = fmaf(a, w0, acc[i][0]);
                acc[i][1] = fmaf(a, w1, acc[i][1]);
                acc[i][2] = fmaf(a, w2, acc[i][2]);
            }
        }
        __syncthreads();
    }
    float b0 = b[tx], b1 = b[tx + 32], b2 = b[tx + 64];
    #pragma unroll
    for (int i = 0; i < 8; i++) {
        int gr = rowbase + ty * 8 + i;
        if (gr < NNODES) {
            float v0 = fmaxf(acc[i][0] + b0, 0.f);
            float v1 = fmaxf(acc[i][1] + b1, 0.f);
            float v2 = fmaxf(acc[i][2] + b2, 0.f);
            int off = gr * HDIM;
            g_x0[off + tx]      = v0; g_xcur[off + tx]      = v0;
            g_x0[off + tx + 32] = v1; g_xcur[off + tx + 32] = v1;
            g_x0[off + tx + 64] = v2; g_xcur[off + tx + 64] = v2;
        }
    }
}

// ---------------- SpMM: agg = D^-1/2 (A+I) D^-1/2 @ xcur ----------------
// init: self-loop contribution + zero BN accumulators
__global__ __launch_bounds__(256) void spmm_init() {
    int i = blockIdx.x * 256 + threadIdx.x;
    if (blockIdx.x == 0 && threadIdx.x < 2 * HDIM) g_sums[threadIdx.x] = 0.f;
    if (i >= NNODES * H4) return;
    int node = i / H4;
    float di = g_dinv[node];
    float s = di * di;
    float4 v = ((const float4*)g_xcur)[i];
    float4 o = make_float4(v.x * s, v.y * s, v.z * s, v.w * s);
    ((float4*)g_agg)[i] = o;
}

// scatter: 8 threads per edge, 3 float4 each, vector red.global.add.v4.f32
__global__ __launch_bounds__(256) void spmm_scatter() {
    int gid = blockIdx.x * 256 + threadIdx.x;
    int e = gid >> 3;
    if (e >= NEDGES) return;
    int part = gid & 7;
    int row = g_row[e], col = g_col[e];
    float nrm = g_norm[e];
    const float4* xs = ((const float4*)g_xcur) + row * H4;
    float4* ag = ((float4*)g_agg) + col * H4;
    #pragma unroll
    for (int j = 0; j < 3; j++) {
        int f4 = j * 8 + part;
        float4 v = xs[f4];
        float a = v.x * nrm, b = v.y * nrm, c = v.z * nrm, d = v.w * nrm;
        asm volatile("red.global.add.v4.f32 [%0], {%1, %2, %3, %4};"
                     :: "l"(ag + f4), "f"(a), "f"(b), "f"(c), "f"(d)
                     : "memory");
    }
}

// ---------------- conv: h2 = (1-B)*h1 + B*(h1 @ W), h1 = 0.9*agg + 0.1*x0 ---
// In-place into g_agg. Same tiling as fc1, K=96.
__global__ __launch_bounds__(256) void conv_gemm(
    const float* __restrict__ W, float betaL)
{
    __shared__ float As[64][32];
    __shared__ float Ws[32][96];
    int tid = threadIdx.x;
    int tx = tid & 31, ty = tid >> 5;
    int rowbase = blockIdx.x * 64;
    float acc[8][3] = {};
    for (int kc = 0; kc < HDIM; kc += 32) {
        #pragma unroll
        for (int i = 0; i < 8; i++) {
            int idx = tid + i * 256;
            int r = idx >> 5, k = idx & 31;
            int gr = rowbase + r;
            float v = 0.f;
            if (gr < NNODES) {
                int off = gr * HDIM + kc + k;
                v = 0.9f * g_agg[off] + 0.1f * g_x0[off];
            }
            As[r][k] = v;
        }
        #pragma unroll
        for (int i = 0; i < 12; i++) {
            int idx = tid + i * 256;
            ((float*)Ws)[idx] = W[kc * HDIM + idx];
        }
        __syncthreads();
        #pragma unroll
        for (int kk = 0; kk < 32; kk++) {
            float w0 = Ws[kk][tx], w1 = Ws[kk][tx + 32], w2 = Ws[kk][tx + 64];
            #pragma unroll
            for (int i = 0; i < 8; i++) {
                float a = As[ty * 8 + i][kk];
                acc[i][0] = fmaf(a, w0, acc[i][0]);
                acc[i][1] = fmaf(a, w1, acc[i][1]);
                acc[i][2] = fmaf(a, w2, acc[i][2]);
            }
        }
        __syncthreads();
    }
    float ob = 1.0f - betaL;
    #pragma unroll
    for (int i = 0; i < 8; i++) {
        int gr = rowbase + ty * 8 + i;
        if (gr < NNODES) {
            #pragma unroll
            for (int j = 0; j < 3; j++) {
                int c = tx + 32 * j;
                int off = gr * HDIM + c;
                float h1 = 0.9f * g_agg[off] + 0.1f * g_x0[off];
                g_agg[off] = ob * h1 + betaL * acc[i][j];
            }
        }
    }
}

// ---------------- BN stats: per-feature sum & sumsq of g_agg ----------------
__global__ __launch_bounds__(256) void bn_stats() {
    __shared__ float ss[HDIM], sq[HDIM];
    int tid = threadIdx.x;
    if (tid < HDIM) { ss[tid] = 0.f; sq[tid] = 0.f; }
    __syncthreads();
    if (tid < 240) {
        int c4 = tid % H4;      // float4-column 0..23
        int rg = tid / H4;      // row group 0..9
        float4 s = make_float4(0, 0, 0, 0);
        float4 q = make_float4(0, 0, 0, 0);
        for (int r = blockIdx.x * 10 + rg; r < NNODES; r += gridDim.x * 10) {
            float4 v = ((const float4*)g_agg)[r * H4 + c4];
            s.x += v.x; s.y += v.y; s.z += v.z; s.w += v.w;
            q.x += v.x * v.x; q.y += v.y * v.y;
            q.z += v.z * v.z; q.w += v.w * v.w;
        }
        int c = c4 * 4;
        atomicAdd(&ss[c + 0], s.x); atomicAdd(&ss[c + 1], s.y);
        atomicAdd(&ss[c + 2], s.z); atomicAdd(&ss[c + 3], s.w);
        atomicAdd(&sq[c + 0], q.x); atomicAdd(&sq[c + 1], q.y);
        atomicAdd(&sq[c + 2], q.z); atomicAdd(&sq[c + 3], q.w);
    }
    __syncthreads();
    if (tid < HDIM) {
        atomicAdd(&g_sums[tid], ss[tid]);
        atomicAdd(&g_sums[HDIM + tid], sq[tid]);
    }
}

// ---------------- BN apply + relu -> g_xcur ----------------
__global__ __launch_bounds__(256) void bn_apply(
    const float* __restrict__ gamma, const float* __restrict__ beta)
{
    __shared__ float sc[HDIM], sh[HDIM];
    int tid = threadIdx.x;
    if (tid < HDIM) {
        float s = g_sums[tid], q = g_sums[HDIM + tid];
        float mean = s * (1.0f / NNODES);
        float var  = q * (1.0f / NNODES) - mean * mean;
        float scl = gamma[tid] * rsqrtf(var + BN_EPSF);
        sc[tid] = scl;
        sh[tid] = beta[tid] - mean * scl;
    }
    __syncthreads();
    int i = blockIdx.x * 256 + tid;
    if (i >= NNODES * H4) return;
    int c = (i % H4) * 4;
    float4 v = ((const float4*)g_agg)[i];
    float4 o;
    o.x = fmaxf(fmaf(v.x, sc[c + 0], sh[c + 0]), 0.f);
    o.y = fmaxf(fmaf(v.y, sc[c + 1], sh[c + 1]), 0.f);
    o.z = fmaxf(fmaf(v.z, sc[c + 2], sh[c + 2]), 0.f);
    o.w = fmaxf(fmaf(v.w, sc[c + 3], sh[c + 3]), 0.f);
    ((float4*)g_xcur)[i] = o;
}

// ---------------- fc2: out = xcur @ W + b ----------------
__global__ __launch_bounds__(256) void fc2_gemm(
    const float* __restrict__ W, const float* __restrict__ b,
    float* __restrict__ out)
{
    __shared__ float As[64][100];      // padded to kill bank conflicts
    __shared__ float Ws[HDIM][OUTDIM];
    int tid = threadIdx.x;
    int rowbase = blockIdx.x * 64;
    #pragma unroll
    for (int i = 0; i < 24; i++) {
        int idx = tid + i * 256;       // 6144 elems
        int r = idx / HDIM, c = idx - r * HDIM;
        int gr = rowbase + r;
        As[r][c] = (gr < NNODES) ? g_xcur[gr * HDIM + c] : 0.f;
    }
    #pragma unroll
    for (int i = 0; i < 15; i++) {
        int idx = tid + i * 256;       // 3840 elems
        int k = idx / OUTDIM, c = idx - k * OUTDIM;
        Ws[k][c] = W[idx];
    }
    __syncthreads();
    int r = tid >> 2;                  // 0..63
    int cg = tid & 3;                  // 0..3 -> cols cg*10..+9
    float acc[10] = {};
    #pragma unroll 4
    for (int k = 0; k < HDIM; k++) {
        float a = As[r][k];
        #pragma unroll
        for (int j = 0; j < 10; j++)
            acc[j] = fmaf(a, Ws[k][cg * 10 + j], acc[j]);
    }
    int gr = rowbase + r;
    if (gr < NNODES) {
        #pragma unroll
        for (int j = 0; j < 10; j++)
            out[gr * OUTDIM + cg * 10 + j] = acc[j] + b[cg * 10 + j];
    }
}

// ---------------- launch ----------------
extern "C" void kernel_launch(void* const* d_in, const int* in_sizes, int n_in,
                              void* d_out, int out_size) {
    const float* x     = (const float*)d_in[0];
    const void*  eidx  = d_in[1];
    const float* fc1w  = (const float*)d_in[2];
    const float* fc1b  = (const float*)d_in[3];
    const float* convw = (const float*)d_in[4];
    const float* gam   = (const float*)d_in[5];
    const float* bet   = (const float*)d_in[6];
    const float* fc2w  = (const float*)d_in[7];
    const float* fc2b  = (const float*)d_in[8];
    float* out = (float*)d_out;

    const int nb_node = (NNODES + 255) / 256;
    const int nb_edge = (NEDGES + 255) / 256;
    const int nb_gemm = (NNODES + 63) / 64;
    const int nb_elem = (NNODES * H4 + 255) / 256;
    const int nb_scat = (NEDGES * 8 + 255) / 256;

    detect_idx<<<1, 256>>>(eidx);
    deg_init<<<nb_node, 256>>>();
    convert_idx<<<nb_edge, 256>>>(eidx);
    dinv_kernel<<<nb_node, 256>>>();
    norm_kernel<<<nb_edge, 256>>>();

    fc1_gemm<<<nb_gemm, 256>>>(x, fc1w, fc1b);

    // beta_l = log(theta/(l+1) + 1), theta = 0.5
    const float betas[3] = {0.40546510810f, 0.22314355131f, 0.15415067982f};
    for (int l = 0; l < 3; l++) {
        spmm_init<<<nb_elem, 256>>>();
        spmm_scatter<<<nb_scat, 256>>>();
        conv_gemm<<<nb_gemm, 256>>>(convw + l * HDIM * HDIM, betas[l]);
        bn_stats<<<592, 256>>>();
        bn_apply<<<nb_elem, 256>>>(gam + l * HDIM, bet + l * HDIM);
    }

    fc2_gemm<<<nb_gemm, 256>>>(fc2w, fc2b, out);
}

// round 3
// speedup vs baseline: 1.0788x; 1.0788x over previous
#include <cuda_runtime.h>
#include <cuda_bf16.h>
#include <math.h>

// ---------------- Problem constants ----------------
#define NNODES 50000
#define NEDGES 800000
#define INDIM  256
#define HDIM   96
#define OUTDIM 40
#define H4     24
#define BN_EPSF 1e-5f

// ---------------- Scratch (device globals) ----------------
__device__ int   g_cnt [NNODES];       // in-degree (no self loop)
__device__ int   g_fill[NNODES];       // fill cursors
__device__ int   g_rowptr[NNODES + 1];
__device__ float g_dinv[NNODES];
__device__ int   g_row [NEDGES];
__device__ int   g_col [NEDGES];
__device__ __align__(16) long long g_csr[NEDGES];   // {row:int32, norm:f32}
__device__ __align__(16) float g_x0  [NNODES * HDIM];
__device__ __align__(16) float g_xcur[NNODES * HDIM];
__device__ __align__(16) float g_agg [NNODES * HDIM];  // h1, then h2 in-place
__device__ float g_sums[2 * HDIM];
__device__ int   g_is64;

// ---------------- f32x2 helpers ----------------
__device__ __forceinline__ unsigned long long fma2(
    unsigned long long a, unsigned long long b, unsigned long long c) {
    unsigned long long d;
    asm("fma.rn.f32x2 %0, %1, %2, %3;" : "=l"(d) : "l"(a), "l"(b), "l"(c));
    return d;
}
__device__ __forceinline__ unsigned long long pack2(float lo, float hi) {
    unsigned long long d;
    asm("mov.b64 %0, {%1, %2};" : "=l"(d) : "f"(lo), "f"(hi));
    return d;
}
__device__ __forceinline__ void unpack2(unsigned long long v, float& lo, float& hi) {
    asm("mov.b64 {%0, %1}, %2;" : "=f"(lo), "=f"(hi) : "l"(v));
}

// ---------------- setup kernels ----------------
__global__ void detect_idx(const void* p) {
    const int* q = (const int*)p;
    __shared__ int s;
    if (threadIdx.x == 0) s = 0;
    __syncthreads();
    int nz = 0;
    for (int i = threadIdx.x; i < 1024; i += 256) nz |= q[2 * i + 1];
    if (nz) atomicOr(&s, 1);
    __syncthreads();
    if (threadIdx.x == 0) g_is64 = (s == 0) ? 1 : 0;
}

__global__ void zero_cnt() {
    int i = blockIdx.x * 256 + threadIdx.x;
    if (i < NNODES) g_cnt[i] = 0;
}

__global__ void convert_idx(const void* p) {
    int e = blockIdx.x * 256 + threadIdx.x;
    if (e >= NEDGES) return;
    int r, c;
    if (g_is64) {
        const long long* q = (const long long*)p;
        r = (int)q[e];
        c = (int)q[(long long)NEDGES + e];
    } else {
        const int* q = (const int*)p;
        r = q[e];
        c = q[NEDGES + e];
    }
    g_row[e] = r;
    g_col[e] = c;
    atomicAdd(&g_cnt[c], 1);
}

__global__ void dinv_kernel() {
    int i = blockIdx.x * 256 + threadIdx.x;
    if (i >= NNODES) return;
    g_dinv[i] = rsqrtf((float)(g_cnt[i] + 1));   // +1 self loop, always > 0
}

// single-block exclusive scan of g_cnt -> g_rowptr; also zero g_fill
#define SCAN_PER 49
__global__ __launch_bounds__(1024) void scan_kernel() {
    __shared__ int part[1024];
    int t = threadIdx.x;
    int base = t * SCAN_PER;
    int sum = 0;
    for (int i = 0; i < SCAN_PER; i++) {
        int idx = base + i;
        if (idx < NNODES) sum += g_cnt[idx];
    }
    part[t] = sum;
    __syncthreads();
    // Hillis-Steele inclusive scan
    for (int d = 1; d < 1024; d <<= 1) {
        int v = (t >= d) ? part[t - d] : 0;
        __syncthreads();
        part[t] += v;
        __syncthreads();
    }
    int run = (t > 0) ? part[t - 1] : 0;  // exclusive prefix for this thread
    for (int i = 0; i < SCAN_PER; i++) {
        int idx = base + i;
        if (idx <= NNODES) g_rowptr[idx] = run;
        if (idx < NNODES) {
            run += g_cnt[idx];
            g_fill[idx] = 0;
        }
    }
}

__global__ void fill_csr() {
    int e = blockIdx.x * 256 + threadIdx.x;
    if (e >= NEDGES) return;
    int r = g_row[e], c = g_col[e];
    int p = g_rowptr[c] + atomicAdd(&g_fill[c], 1);
    float nrm = g_dinv[r] * g_dinv[c];
    g_csr[p] = ((long long)__float_as_int(nrm) << 32) | (unsigned int)r;
}

// ---------------- fc1: relu(X @ W + b) -> g_x0, g_xcur (f32x2) ----------------
// Block: 128 rows x 96 cols. 256 threads: tx=tid&15 (6 cols: tx+16j),
// ty=tid>>4 (8 rows: ty*8.. as 4 packed pairs). K chunks of 32, A transposed.
#define APAD 130
__global__ __launch_bounds__(256) void fc1_gemm(
    const float* __restrict__ X, const float* __restrict__ W,
    const float* __restrict__ b)
{
    __shared__ __align__(16) float As[32 * APAD];   // [k][r] transposed
    __shared__ __align__(16) float Ws[32 * HDIM];   // [k][c]
    int tid = threadIdx.x;
    int tx = tid & 15, ty = tid >> 4;
    int rowbase = blockIdx.x * 128;
    unsigned long long acc[4][6];
    #pragma unroll
    for (int p = 0; p < 4; p++)
        #pragma unroll
        for (int j = 0; j < 6; j++) acc[p][j] = 0ULL;

    for (int kc = 0; kc < INDIM; kc += 32) {
        #pragma unroll
        for (int i = 0; i < 4; i++) {
            int idx = tid + i * 256;         // 0..1023
            int r = idx >> 3, kq = idx & 7;  // 128 rows x 8 quads
            int gr = rowbase + r;
            float4 v = make_float4(0.f, 0.f, 0.f, 0.f);
            if (gr < NNODES)
                v = *(const float4*)(X + (size_t)gr * INDIM + kc + kq * 4);
            As[(kq * 4 + 0) * APAD + r] = v.x;
            As[(kq * 4 + 1) * APAD + r] = v.y;
            As[(kq * 4 + 2) * APAD + r] = v.z;
            As[(kq * 4 + 3) * APAD + r] = v.w;
        }
        #pragma unroll
        for (int i = 0; i < 12; i++) {
            int idx = tid + i * 256;
            Ws[idx] = W[kc * HDIM + idx];
        }
        __syncthreads();
        #pragma unroll 8
        for (int kk = 0; kk < 32; kk++) {
            unsigned long long a[4], wp[6];
            #pragma unroll
            for (int p = 0; p < 4; p++)
                a[p] = *(const unsigned long long*)&As[kk * APAD + ty * 8 + 2 * p];
            #pragma unroll
            for (int j = 0; j < 6; j++) {
                float w = Ws[kk * HDIM + tx + 16 * j];
                wp[j] = pack2(w, w);
            }
            #pragma unroll
            for (int p = 0; p < 4; p++)
                #pragma unroll
                for (int j = 0; j < 6; j++)
                    acc[p][j] = fma2(a[p], wp[j], acc[p][j]);
        }
        __syncthreads();
    }
    #pragma unroll
    for (int p = 0; p < 4; p++) {
        int r0 = rowbase + ty * 8 + 2 * p;
        #pragma unroll
        for (int j = 0; j < 6; j++) {
            int c = tx + 16 * j;
            float lo, hi;
            unpack2(acc[p][j], lo, hi);
            float bb = b[c];
            if (r0 < NNODES) {
                float v = fmaxf(lo + bb, 0.f);
                g_x0[r0 * HDIM + c] = v;
                g_xcur[r0 * HDIM + c] = v;
            }
            if (r0 + 1 < NNODES) {
                float v = fmaxf(hi + bb, 0.f);
                g_x0[(r0 + 1) * HDIM + c] = v;
                g_xcur[(r0 + 1) * HDIM + c] = v;
            }
        }
    }
}

// ---------------- pull SpMM: h1 = 0.9*(norm-agg incl self) + 0.1*x0 ----------
// warp per node; lane handles features {lane, lane+32, lane+64}
__global__ __launch_bounds__(256) void pull_kernel() {
    int gtid = blockIdx.x * 256 + threadIdx.x;
    if (blockIdx.x == 0 && threadIdx.x < 2 * HDIM) g_sums[threadIdx.x] = 0.f;
    int n = gtid >> 5;
    if (n >= NNODES) return;
    int lane = gtid & 31;
    int s = g_rowptr[n], e = g_rowptr[n + 1];
    float di = g_dinv[n];
    float sl = di * di;
    const float* xc = g_xcur + (size_t)n * HDIM;
    float a0 = sl * xc[lane];
    float a1 = sl * xc[lane + 32];
    float a2 = sl * xc[lane + 64];
    int p = s;
    // unroll by 2 for MLP
    for (; p + 2 <= e; p += 2) {
        long long v0 = g_csr[p], v1 = g_csr[p + 1];
        int r0 = (int)v0, r1 = (int)v1;
        float n0 = __int_as_float((int)(v0 >> 32));
        float n1 = __int_as_float((int)(v1 >> 32));
        const float* x0p = g_xcur + (size_t)r0 * HDIM;
        const float* x1p = g_xcur + (size_t)r1 * HDIM;
        float b0 = x0p[lane], b1 = x0p[lane + 32], b2 = x0p[lane + 64];
        float c0 = x1p[lane], c1 = x1p[lane + 32], c2 = x1p[lane + 64];
        a0 = fmaf(n0, b0, a0); a1 = fmaf(n0, b1, a1); a2 = fmaf(n0, b2, a2);
        a0 = fmaf(n1, c0, a0); a1 = fmaf(n1, c1, a1); a2 = fmaf(n1, c2, a2);
    }
    if (p < e) {
        long long v0 = g_csr[p];
        int r0 = (int)v0;
        float n0 = __int_as_float((int)(v0 >> 32));
        const float* x0p = g_xcur + (size_t)r0 * HDIM;
        a0 = fmaf(n0, x0p[lane], a0);
        a1 = fmaf(n0, x0p[lane + 32], a1);
        a2 = fmaf(n0, x0p[lane + 64], a2);
    }
    const float* x0n = g_x0 + (size_t)n * HDIM;
    float* ag = g_agg + (size_t)n * HDIM;
    ag[lane]      = fmaf(0.9f, a0, 0.1f * x0n[lane]);
    ag[lane + 32] = fmaf(0.9f, a1, 0.1f * x0n[lane + 32]);
    ag[lane + 64] = fmaf(0.9f, a2, 0.1f * x0n[lane + 64]);
}

// ---------------- conv: h2 = (1-B)*h1 + B*(h1@W), fused BN stats ------------
__global__ __launch_bounds__(256) void conv_gemm(
    const float* __restrict__ W, float betaL)
{
    __shared__ __align__(16) float As[32 * APAD];
    __shared__ __align__(16) float Ws[32 * HDIM];
    __shared__ float bsum[HDIM], bsq[HDIM];
    int tid = threadIdx.x;
    int tx = tid & 15, ty = tid >> 4;
    int rowbase = blockIdx.x * 128;
    if (tid < HDIM) { bsum[tid] = 0.f; bsq[tid] = 0.f; }
    unsigned long long acc[4][6];
    #pragma unroll
    for (int p = 0; p < 4; p++)
        #pragma unroll
        for (int j = 0; j < 6; j++) acc[p][j] = 0ULL;

    for (int kc = 0; kc < HDIM; kc += 32) {
        #pragma unroll
        for (int i = 0; i < 4; i++) {
            int idx = tid + i * 256;
            int r = idx >> 3, kq = idx & 7;
            int gr = rowbase + r;
            float4 v = make_float4(0.f, 0.f, 0.f, 0.f);
            if (gr < NNODES)
                v = *(const float4*)(g_agg + (size_t)gr * HDIM + kc + kq * 4);
            As[(kq * 4 + 0) * APAD + r] = v.x;
            As[(kq * 4 + 1) * APAD + r] = v.y;
            As[(kq * 4 + 2) * APAD + r] = v.z;
            As[(kq * 4 + 3) * APAD + r] = v.w;
        }
        #pragma unroll
        for (int i = 0; i < 12; i++) {
            int idx = tid + i * 256;
            Ws[idx] = W[kc * HDIM + idx];
        }
        __syncthreads();
        #pragma unroll 8
        for (int kk = 0; kk < 32; kk++) {
            unsigned long long a[4], wp[6];
            #pragma unroll
            for (int p = 0; p < 4; p++)
                a[p] = *(const unsigned long long*)&As[kk * APAD + ty * 8 + 2 * p];
            #pragma unroll
            for (int j = 0; j < 6; j++) {
                float w = Ws[kk * HDIM + tx + 16 * j];
                wp[j] = pack2(w, w);
            }
            #pragma unroll
            for (int p = 0; p < 4; p++)
                #pragma unroll
                for (int j = 0; j < 6; j++)
                    acc[p][j] = fma2(a[p], wp[j], acc[p][j]);
        }
        __syncthreads();
    }
    float ob = 1.0f - betaL;
    float s[6] = {}, q[6] = {};
    #pragma unroll
    for (int p = 0; p < 4; p++) {
        int r0 = rowbase + ty * 8 + 2 * p;
        #pragma unroll
        for (int j = 0; j < 6; j++) {
            int c = tx + 16 * j;
            float lo, hi;
            unpack2(acc[p][j], lo, hi);
            if (r0 < NNODES) {
                float h1 = g_agg[(size_t)r0 * HDIM + c];
                float h2 = fmaf(ob, h1, betaL * lo);
                g_agg[(size_t)r0 * HDIM + c] = h2;
                s[j] += h2; q[j] += h2 * h2;
            }
            if (r0 + 1 < NNODES) {
                float h1 = g_agg[(size_t)(r0 + 1) * HDIM + c];
                float h2 = fmaf(ob, h1, betaL * hi);
                g_agg[(size_t)(r0 + 1) * HDIM + c] = h2;
                s[j] += h2; q[j] += h2 * h2;
            }
        }
    }
    __syncthreads();   // bsum/bsq zeroed before atomics (init was pre-mainloop sync anyway)
    #pragma unroll
    for (int j = 0; j < 6; j++) {
        int c = tx + 16 * j;
        atomicAdd(&bsum[c], s[j]);
        atomicAdd(&bsq[c], q[j]);
    }
    __syncthreads();
    if (tid < HDIM)            atomicAdd(&g_sums[tid], bsum[tid]);
    else if (tid < 2 * HDIM)   atomicAdd(&g_sums[tid], bsq[tid - HDIM]);
}

// ---------------- BN apply + relu -> g_xcur ----------------
__global__ __launch_bounds__(256) void bn_apply(
    const float* __restrict__ gamma, const float* __restrict__ beta)
{
    __shared__ float sc[HDIM], sh[HDIM];
    int tid = threadIdx.x;
    if (tid < HDIM) {
        float s = g_sums[tid], q = g_sums[HDIM + tid];
        float mean = s * (1.0f / NNODES);
        float var  = q * (1.0f / NNODES) - mean * mean;
        float scl = gamma[tid] * rsqrtf(var + BN_EPSF);
        sc[tid] = scl;
        sh[tid] = beta[tid] - mean * scl;
    }
    __syncthreads();
    int i = blockIdx.x * 256 + tid;
    if (i >= NNODES * H4) return;
    int c = (i % H4) * 4;
    float4 v = ((const float4*)g_agg)[i];
    float4 o;
    o.x = fmaxf(fmaf(v.x, sc[c + 0], sh[c + 0]), 0.f);
    o.y = fmaxf(fmaf(v.y, sc[c + 1], sh[c + 1]), 0.f);
    o.z = fmaxf(fmaf(v.z, sc[c + 2], sh[c + 2]), 0.f);
    o.w = fmaxf(fmaf(v.w, sc[c + 3], sh[c + 3]), 0.f);
    ((float4*)g_xcur)[i] = o;
}

// ---------------- fc2: out = xcur @ W + b ----------------
__global__ __launch_bounds__(256) void fc2_gemm(
    const float* __restrict__ W, const float* __restrict__ b,
    float* __restrict__ out)
{
    __shared__ float As[64][100];
    __shared__ float Ws[HDIM][OUTDIM];
    int tid = threadIdx.x;
    int rowbase = blockIdx.x * 64;
    #pragma unroll
    for (int i = 0; i < 24; i++) {
        int idx = tid + i * 256;
        int r = idx / HDIM, c = idx - r * HDIM;
        int gr = rowbase + r;
        As[r][c] = (gr < NNODES) ? g_xcur[(size_t)gr * HDIM + c] : 0.f;
    }
    #pragma unroll
    for (int i = 0; i < 15; i++) {
        int idx = tid + i * 256;
        int k = idx / OUTDIM, c = idx - k * OUTDIM;
        Ws[k][c] = W[idx];
    }
    __syncthreads();
    int r = tid >> 2;
    int cg = tid & 3;
    float acc[10] = {};
    #pragma unroll 4
    for (int k = 0; k < HDIM; k++) {
        float a = As[r][k];
        #pragma unroll
        for (int j = 0; j < 10; j++)
            acc[j] = fmaf(a, Ws[k][cg * 10 + j], acc[j]);
    }
    int gr = rowbase + r;
    if (gr < NNODES) {
        #pragma unroll
        for (int j = 0; j < 10; j++)
            out[(size_t)gr * OUTDIM + cg * 10 + j] = acc[j] + b[cg * 10 + j];
    }
}

// ---------------- launch ----------------
extern "C" void kernel_launch(void* const* d_in, const int* in_sizes, int n_in,
                              void* d_out, int out_size) {
    const float* x     = (const float*)d_in[0];
    const void*  eidx  = d_in[1];
    const float* fc1w  = (const float*)d_in[2];
    const float* fc1b  = (const float*)d_in[3];
    const float* convw = (const float*)d_in[4];
    const float* gam   = (const float*)d_in[5];
    const float* bet   = (const float*)d_in[6];
    const float* fc2w  = (const float*)d_in[7];
    const float* fc2b  = (const float*)d_in[8];
    float* out = (float*)d_out;

    const int nb_node = (NNODES + 255) / 256;
    const int nb_edge = (NEDGES + 255) / 256;
    const int nb_g128 = (NNODES + 127) / 128;
    const int nb_g64  = (NNODES + 63) / 64;
    const int nb_elem = (NNODES * H4 + 255) / 256;
    const int nb_pull = (NNODES * 32 + 255) / 256;

    detect_idx<<<1, 256>>>(eidx);
    zero_cnt<<<nb_node, 256>>>();
    convert_idx<<<nb_edge, 256>>>(eidx);
    dinv_kernel<<<nb_node, 256>>>();
    scan_kernel<<<1, 1024>>>();
    fill_csr<<<nb_edge, 256>>>();

    fc1_gemm<<<nb_g128, 256>>>(x, fc1w, fc1b);

    const float betas[3] = {0.40546510810f, 0.22314355131f, 0.15415067982f};
    for (int l = 0; l < 3; l++) {
        pull_kernel<<<nb_pull, 256>>>();
        conv_gemm<<<nb_g128, 256>>>(convw + l * HDIM * HDIM, betas[l]);
        bn_apply<<<nb_elem, 256>>>(gam + l * HDIM, bet + l * HDIM);
    }

    fc2_gemm<<<nb_g64, 256>>>(fc2w, fc2b, out);
}